// round 17
// baseline (speedup 1.0000x reference)
#include <cuda_runtime.h>
#include <cuda_bf16.h>
#include <mma.h>
#include <cstdint>

using namespace nvcuda;

#define EPS_BN 1e-5f
typedef uint32_t u32;

// ---------------- scratch (static; no allocation allowed) -------------------
__device__ u32   g_th32[2 * 8 * 256 * 256 / 2];  // conv1 out hi bf16, packed pairs
__device__ u32   g_tl32[2 * 8 * 256 * 256 / 2];  // conv1 out lo bf16, packed pairs
__device__ float g_pm[4096 * 2];                 // softmax partials (max) per (row, half)
__device__ float g_ps1[4096 * 2];                // sum e^(x-m)
__device__ float g_ps2[4096 * 2];                // sum (x-m)e^(x-m)
__device__ float g_ew[8 * 256];                  // entropy gate
__device__ float g_mw[8 * 256];                  // mi gate

__device__ __forceinline__ float sigmoidf(float x) { return 1.f / (1.f + __expf(-x)); }

// packed split: 2 fp32 -> (hi bf16 pair, lo bf16 pair); low 16 bits = element 0
__device__ __forceinline__ void split2(float x0, float x1, u32& h, u32& l) {
    __nv_bfloat162 H = __float22bfloat162_rn(make_float2(x0, x1));
    float2 Hf = __bfloat1622float2(H);
    __nv_bfloat162 L = __float22bfloat162_rn(make_float2(x0 - Hf.x, x1 - Hf.y));
    h = *(u32*)&H;
    l = *(u32*)&L;
}

typedef wmma::fragment<wmma::matrix_a, 16, 16, 16, __nv_bfloat16, wmma::row_major> FragA;
typedef wmma::fragment<wmma::matrix_b, 16, 16, 16, __nv_bfloat16, wmma::row_major> FragB;
typedef wmma::fragment<wmma::accumulator, 16, 16, 16, float> FragC;

// ---- smem layouts (bytes) ----
// conv1 (single K=256 phase): Ah[64][264]b16, Al; Bh[256][136]b16, Bl.
//   epilogue scratch float[64][136] overlays Bh.
#define C1_AH 0
#define C1_AL 33792
#define C1_BH 67584
#define C1_BL 137216
#define C1_SMEM 206848
// conv2 (2 serial K=256 chunks): Ah[64][264]b16, Al; Bh[256][72]b16, Bl; sc[512]f32.
//   epilogue scratch float[64][72] overlays Bh.
#define C2_AH 0
#define C2_AL 33792
#define C2_BH 67584
#define C2_BL 104448
#define C2_SC 141312
#define C2_SMEM 143360

// ---------------------------------------------------------------------------
// conv1: Y = relu(BN(W @ X)); per CTA: M=64 (o), N=128 (n), K=256 single phase.
// Grid (4,2,16) x 256 thr (8 warps, 2x4, warp tile 32x32).
// 3-pass bf16 hi/lo -> fp32 acc. Epilogue: BN+ReLU fp32, entropy half-row
// partials, packed hi|lo output for conv2.
// ---------------------------------------------------------------------------
__global__ __launch_bounds__(256) void conv1_wm(
    const float* __restrict__ vis, const float* __restrict__ text,
    const float* __restrict__ W, const float* __restrict__ bt,
    const float* __restrict__ g1, const float* __restrict__ b1,
    const float* __restrict__ m1, const float* __restrict__ v1)
{
    extern __shared__ char smem[];
    __nv_bfloat16* Ah = (__nv_bfloat16*)(smem + C1_AH);
    __nv_bfloat16* Al = (__nv_bfloat16*)(smem + C1_AL);
    __nv_bfloat16* Bh = (__nv_bfloat16*)(smem + C1_BH);
    __nv_bfloat16* Bl = (__nv_bfloat16*)(smem + C1_BL);

    const int tid = threadIdx.x, warp = tid >> 5;
    const int wm = warp >> 2, wn = warp & 3;
    const int bm = blockIdx.x * 64, n0 = blockIdx.y * 128, zb = blockIdx.z;
    const float* __restrict__ X =
        (zb >= 8) ? (text + (size_t)(zb - 8) * 65536) : (vis + (size_t)zb * 65536);

    // ---- stage A = W[bm..+64)[0..256) hi/lo: r = tid/4, 64 cols each ----
    {
        const int r = tid >> 2, k0 = (tid & 3) * 64;
        const float4* src = (const float4*)(W + (size_t)(bm + r) * 256 + k0);
        u32* rh = (u32*)(Ah + r * 264 + k0);
        u32* rl = (u32*)(Al + r * 264 + k0);
        #pragma unroll
        for (int i = 0; i < 16; i++) {
            float4 v = src[i];
            u32 h0, l0, h1, l1;
            split2(v.x, v.y, h0, l0);
            split2(v.z, v.w, h1, l1);
            rh[2 * i] = h0; rh[2 * i + 1] = h1;
            rl[2 * i] = l0; rl[2 * i + 1] = l1;
        }
    }
    // ---- stage B = X[0..256)[n0..+128) hi/lo: one k-row per thread ----
    {
        const int r = tid;
        const float4* src = (const float4*)(X + (size_t)r * 256 + n0);
        u32* rh = (u32*)(Bh + r * 136);
        u32* rl = (u32*)(Bl + r * 136);
        #pragma unroll
        for (int i = 0; i < 32; i++) {
            float4 v = src[i];
            u32 h0, l0, h1, l1;
            split2(v.x, v.y, h0, l0);
            split2(v.z, v.w, h1, l1);
            rh[2 * i] = h0; rh[2 * i + 1] = h1;
            rl[2 * i] = l0; rl[2 * i + 1] = l1;
        }
    }
    __syncthreads();

    FragC acc[2][2];
    #pragma unroll
    for (int i = 0; i < 2; i++)
        #pragma unroll
        for (int j = 0; j < 2; j++) wmma::fill_fragment(acc[i][j], 0.f);

    #pragma unroll
    for (int ks = 0; ks < 16; ks++) {
        FragA ah[2], al[2];
        #pragma unroll
        for (int i = 0; i < 2; i++) {
            wmma::load_matrix_sync(ah[i], Ah + (wm * 32 + 16 * i) * 264 + ks * 16, 264);
            wmma::load_matrix_sync(al[i], Al + (wm * 32 + 16 * i) * 264 + ks * 16, 264);
        }
        #pragma unroll
        for (int j = 0; j < 2; j++) {
            FragB bh, bl;
            wmma::load_matrix_sync(bh, Bh + (ks * 16) * 136 + wn * 32 + 16 * j, 136);
            wmma::load_matrix_sync(bl, Bl + (ks * 16) * 136 + wn * 32 + 16 * j, 136);
            #pragma unroll
            for (int i = 0; i < 2; i++) {
                wmma::mma_sync(acc[i][j], ah[i], bh, acc[i][j]);
                wmma::mma_sync(acc[i][j], ah[i], bl, acc[i][j]);
                wmma::mma_sync(acc[i][j], al[i], bh, acc[i][j]);
            }
        }
    }
    __syncthreads();

    // ---- epilogue: dump acc to scratch, BN+ReLU, entropy partial, store ----
    float* scr = (float*)(smem + C1_BH);  // 64 x 136 fp32
    #pragma unroll
    for (int i = 0; i < 2; i++)
        #pragma unroll
        for (int j = 0; j < 2; j++)
            wmma::store_matrix_sync(scr + (wm * 32 + 16 * i) * 136 + wn * 32 + 16 * j,
                                    acc[i][j], 136, wmma::mem_row_major);
    __syncthreads();

    {
        const int row = tid >> 2, q = tid & 3;   // 4 threads per 128-wide half-row
        const int o = bm + row;
        const float s = g1[o] * rsqrtf(v1[o] + EPS_BN);
        const float sh = (bt[o] - m1[o]) * s + b1[o];
        float y[32];
        #pragma unroll
        for (int j = 0; j < 32; j++)
            y[j] = fmaxf(fmaf(scr[row * 136 + q * 32 + j], s, sh), 0.f);

        // packed hi|lo store (u32 = 2 bf16)
        const size_t base = ((size_t)zb * 65536 + (size_t)o * 256 + n0 + q * 32) / 2;
        u32* dh = g_th32 + base;
        u32* dl = g_tl32 + base;
        #pragma unroll
        for (int g = 0; g < 4; g++) {
            u32 hw[4], lw[4];
            #pragma unroll
            for (int p = 0; p < 4; p++)
                split2(y[8 * g + 2 * p], y[8 * g + 2 * p + 1], hw[p], lw[p]);
            *(uint4*)(dh + 4 * g) = make_uint4(hw[0], hw[1], hw[2], hw[3]);
            *(uint4*)(dl + 4 * g) = make_uint4(lw[0], lw[1], lw[2], lw[3]);
        }

        // entropy partial over this 128-wide half-row (4 threads x 32 vals, quad in-warp)
        float mx = y[0];
        #pragma unroll
        for (int j = 1; j < 32; j++) mx = fmaxf(mx, y[j]);
        mx = fmaxf(mx, __shfl_xor_sync(0xffffffffu, mx, 1));
        mx = fmaxf(mx, __shfl_xor_sync(0xffffffffu, mx, 2));
        float s1 = 0.f, s2 = 0.f;
        #pragma unroll
        for (int j = 0; j < 32; j++) {
            float u = y[j] - mx;
            float e = __expf(u);
            s1 += e;
            s2 += u * e;
        }
        s1 += __shfl_xor_sync(0xffffffffu, s1, 1);
        s2 += __shfl_xor_sync(0xffffffffu, s2, 1);
        s1 += __shfl_xor_sync(0xffffffffu, s1, 2);
        s2 += __shfl_xor_sync(0xffffffffu, s2, 2);
        if (q == 0) {
            const int idx = (zb * 256 + o) * 2 + blockIdx.y;
            g_pm[idx] = mx;
            g_ps1[idx] = s1;
            g_ps2[idx] = s2;
        }
    }
}

// ---------------------------------------------------------------------------
// gates: exact 2-way LSE merge -> A = S2/S1 - ln S1; entropy + mi MLP chains.
// ---------------------------------------------------------------------------
__device__ __forceinline__ float mergeA(int r2)
{
    float m0 = g_pm[r2], m1 = g_pm[r2 + 1];
    float a0 = g_ps1[r2], a1 = g_ps1[r2 + 1];
    float c0 = g_ps2[r2], c1 = g_ps2[r2 + 1];
    float M = fmaxf(m0, m1);
    float e0 = __expf(m0 - M), e1 = __expf(m1 - M);
    float S1 = a0 * e0 + a1 * e1;
    float S2 = (c0 + (m0 - M) * a0) * e0 + (c1 + (m1 - M) * a1) * e1;
    return S2 / S1 - logf(S1);
}

__global__ __launch_bounds__(512) void gates_kernel(
    const float* __restrict__ We1, const float* __restrict__ be1,
    const float* __restrict__ We2, const float* __restrict__ be2,
    const float* __restrict__ Wm1, const float* __restrict__ bm1,
    const float* __restrict__ Wm2, const float* __restrict__ bm2)
{
    __shared__ float xs[512];
    __shared__ float h1[256];

    const int bid = blockIdx.x;
    const int branch = bid >> 3, b = bid & 7;
    const int tid = threadIdx.x, warp = tid >> 5, lane = tid & 31;

    if (tid < 256) {
        const int c = tid;
        float Av = mergeA((b * 256 + c) * 2);
        float At = mergeA(((8 + b) * 256 + c) * 2);
        if (branch == 0) { xs[c] = -Av; xs[256 + c] = -At; }
        else              xs[c] = Av + At;
    }
    __syncthreads();

    const int j0 = warp * 16;
    {
        const float* __restrict__ W1 = branch ? Wm1 : We1;
        const float* __restrict__ bb1 = branch ? bm1 : be1;
        float acc[16];
        #pragma unroll
        for (int q = 0; q < 16; q++) acc[q] = 0.f;
        if (branch == 0) {
            #pragma unroll
            for (int i = 0; i < 16; i++) {
                float x = xs[lane + 32 * i];
                #pragma unroll
                for (int q = 0; q < 16; q++) acc[q] += W1[(j0 + q) * 512 + lane + 32 * i] * x;
            }
        } else {
            #pragma unroll
            for (int i = 0; i < 8; i++) {
                float x = xs[lane + 32 * i];
                #pragma unroll
                for (int q = 0; q < 16; q++) acc[q] += W1[(j0 + q) * 256 + lane + 32 * i] * x;
            }
        }
        #pragma unroll
        for (int q = 0; q < 16; q++)
            #pragma unroll
            for (int off = 16; off; off >>= 1) acc[q] += __shfl_xor_sync(0xffffffffu, acc[q], off);
        if (lane == 0) {
            #pragma unroll
            for (int q = 0; q < 16; q++) h1[j0 + q] = fmaxf(acc[q] + bb1[j0 + q], 0.f);
        }
    }
    __syncthreads();
    {
        const float* __restrict__ W2 = branch ? Wm2 : We2;
        const float* __restrict__ bb2 = branch ? bm2 : be2;
        float acc[16];
        #pragma unroll
        for (int q = 0; q < 16; q++) acc[q] = 0.f;
        #pragma unroll
        for (int i = 0; i < 8; i++) {
            float x = h1[lane + 32 * i];
            #pragma unroll
            for (int q = 0; q < 16; q++) acc[q] += W2[(j0 + q) * 256 + lane + 32 * i] * x;
        }
        #pragma unroll
        for (int q = 0; q < 16; q++)
            #pragma unroll
            for (int off = 16; off; off >>= 1) acc[q] += __shfl_xor_sync(0xffffffffu, acc[q], off);
        if (lane == 0) {
            float* out = branch ? g_mw : g_ew;
            #pragma unroll
            for (int q = 0; q < 16; q++) out[b * 256 + j0 + q] = sigmoidf(acc[q] + bb2[j0 + q]);
        }
    }
}

// ---------------------------------------------------------------------------
// conv2: out = relu(BN((Wf*sc) @ T)); per CTA M=64, N=64, K=512 (2 chunks of 256).
// Grid (4,4,8) x 256 thr (8 warps, 2x4, warp tile 32x16). Chunk = tensor half.
// Gates folded into A in fp32 (exact). B = raw copy of packed hi|lo conv1 out.
// ---------------------------------------------------------------------------
__global__ __launch_bounds__(256) void conv2_wm(
    const float* __restrict__ Wf, const float* __restrict__ bf,
    const float* __restrict__ g2, const float* __restrict__ b2,
    const float* __restrict__ m2, const float* __restrict__ v2,
    float* __restrict__ out)
{
    extern __shared__ char smem[];
    __nv_bfloat16* Ah = (__nv_bfloat16*)(smem + C2_AH);
    __nv_bfloat16* Al = (__nv_bfloat16*)(smem + C2_AL);
    __nv_bfloat16* Bh = (__nv_bfloat16*)(smem + C2_BH);
    __nv_bfloat16* Bl = (__nv_bfloat16*)(smem + C2_BL);
    float* sc = (float*)(smem + C2_SC);

    const int tid = threadIdx.x, warp = tid >> 5;
    const int wm = warp >> 2, wn = warp & 3;
    const int bm = blockIdx.x * 64, n0 = blockIdx.y * 64, b = blockIdx.z;

    {
        const int c = tid;
        float e = g_ew[b * 256 + c], m = g_mw[b * 256 + c];
        sc[c] = e * m;
        sc[c + 256] = (1.f - e) * m;
    }
    __syncthreads();

    FragC acc[2];
    #pragma unroll
    for (int i = 0; i < 2; i++) wmma::fill_fragment(acc[i], 0.f);

    #pragma unroll 1
    for (int chunk = 0; chunk < 2; chunk++) {
        // stage A = Wf*sc, rows bm..+64, cols chunk*256..+256, hi/lo
        {
            const int r = tid >> 2, k0 = (tid & 3) * 64;
            const float4* src = (const float4*)(Wf + (size_t)(bm + r) * 512 + chunk * 256 + k0);
            const float4* gsc = (const float4*)(sc + chunk * 256 + k0);
            u32* rh = (u32*)(Ah + r * 264 + k0);
            u32* rl = (u32*)(Al + r * 264 + k0);
            #pragma unroll
            for (int i = 0; i < 16; i++) {
                float4 v = src[i];
                float4 g = gsc[i];
                u32 h0, l0, h1, l1;
                split2(v.x * g.x, v.y * g.y, h0, l0);
                split2(v.z * g.z, v.w * g.w, h1, l1);
                rh[2 * i] = h0; rh[2 * i + 1] = h1;
                rl[2 * i] = l0; rl[2 * i + 1] = l1;
            }
        }
        // stage B: raw copy of packed hi|lo; chunk selects tensor (0=vis, 1=text)
        {
            const int r = tid;  // k-row within chunk = channel
            const size_t off = ((size_t)(chunk * 8 + b) * 65536 + (size_t)r * 256 + n0) / 2;
            const uint4* sh4 = (const uint4*)(g_th32 + off);
            const uint4* sl4 = (const uint4*)(g_tl32 + off);
            uint4* rh = (uint4*)(Bh + r * 72);
            uint4* rl = (uint4*)(Bl + r * 72);
            #pragma unroll
            for (int i = 0; i < 8; i++) { rh[i] = sh4[i]; rl[i] = sl4[i]; }
        }
        __syncthreads();

        #pragma unroll
        for (int ks = 0; ks < 16; ks++) {
            FragA ah[2], al[2];
            #pragma unroll
            for (int i = 0; i < 2; i++) {
                wmma::load_matrix_sync(ah[i], Ah + (wm * 32 + 16 * i) * 264 + ks * 16, 264);
                wmma::load_matrix_sync(al[i], Al + (wm * 32 + 16 * i) * 264 + ks * 16, 264);
            }
            FragB bh, bl;
            wmma::load_matrix_sync(bh, Bh + (ks * 16) * 72 + wn * 16, 72);
            wmma::load_matrix_sync(bl, Bl + (ks * 16) * 72 + wn * 16, 72);
            #pragma unroll
            for (int i = 0; i < 2; i++) {
                wmma::mma_sync(acc[i], ah[i], bh, acc[i]);
                wmma::mma_sync(acc[i], ah[i], bl, acc[i]);
                wmma::mma_sync(acc[i], al[i], bh, acc[i]);
            }
        }
        __syncthreads();
    }

    // ---- epilogue ----
    float* scr = (float*)(smem + C2_BH);  // 64 x 72 fp32
    #pragma unroll
    for (int i = 0; i < 2; i++)
        wmma::store_matrix_sync(scr + (wm * 32 + 16 * i) * 72 + wn * 16,
                                acc[i], 72, wmma::mem_row_major);
    __syncthreads();

    {
        const int row = tid >> 2, q = tid & 3;
        const int o = bm + row;
        const float s = g2[o] * rsqrtf(v2[o] + EPS_BN);
        const float sh = (bf[o] - m2[o]) * s + b2[o];
        float* dst = out + (size_t)(b * 256 + o) * 256 + n0 + q * 16;
        #pragma unroll
        for (int p = 0; p < 4; p++) {
            float4 y;
            y.x = fmaxf(fmaf(scr[row * 72 + q * 16 + 4 * p + 0], s, sh), 0.f);
            y.y = fmaxf(fmaf(scr[row * 72 + q * 16 + 4 * p + 1], s, sh), 0.f);
            y.z = fmaxf(fmaf(scr[row * 72 + q * 16 + 4 * p + 2], s, sh), 0.f);
            y.w = fmaxf(fmaf(scr[row * 72 + q * 16 + 4 * p + 3], s, sh), 0.f);
            *(float4*)(dst + 4 * p) = y;
        }
    }
}

// ---------------------------------------------------------------------------
extern "C" void kernel_launch(void* const* d_in, const int* in_sizes, int n_in,
                              void* d_out, int out_size)
{
    const float* vis  = (const float*)d_in[0];
    const float* text = (const float*)d_in[1];
    const float* Wt   = (const float*)d_in[2];
    const float* bt   = (const float*)d_in[3];
    const float* g1   = (const float*)d_in[4];
    const float* b1   = (const float*)d_in[5];
    const float* m1   = (const float*)d_in[6];
    const float* v1   = (const float*)d_in[7];
    const float* We1  = (const float*)d_in[8];
    const float* be1  = (const float*)d_in[9];
    const float* We2  = (const float*)d_in[10];
    const float* be2  = (const float*)d_in[11];
    const float* Wm1  = (const float*)d_in[12];
    const float* bm1  = (const float*)d_in[13];
    const float* Wm2  = (const float*)d_in[14];
    const float* bm2  = (const float*)d_in[15];
    const float* Wf   = (const float*)d_in[16];
    const float* bf   = (const float*)d_in[17];
    const float* g2   = (const float*)d_in[18];
    const float* b2   = (const float*)d_in[19];
    const float* m2   = (const float*)d_in[20];
    const float* v2   = (const float*)d_in[21];
    float* out = (float*)d_out;

    cudaFuncSetAttribute(conv1_wm, cudaFuncAttributeMaxDynamicSharedMemorySize, C1_SMEM);
    cudaFuncSetAttribute(conv2_wm, cudaFuncAttributeMaxDynamicSharedMemorySize, C2_SMEM);

    conv1_wm<<<dim3(4, 2, 16), 256, C1_SMEM>>>(vis, text, Wt, bt, g1, b1, m1, v1);
    gates_kernel<<<16, 512>>>(We1, be1, We2, be2, Wm1, bm1, Wm2, bm2);
    conv2_wm<<<dim3(4, 4, 8), 256, C2_SMEM>>>(Wf, bf, g2, b2, m2, v2, out);
}